// round 12
// baseline (speedup 1.0000x reference)
#include <cuda_runtime.h>
#include <math.h>

#define H 256
#define W 256
#define V 192
#define D 256
#define S 256
#define HW (H*W)
#define PW 264              /* padded stride: data at [2,257], frame zeros [0,259] */

#define SQRT2_D 1.4142135623730951
#define DPf     ((float)(2.0 * SQRT2_D * 128.0 / 255.0))   /* sample spacing, px */
#define OFFf    ((float)(-SQRT2_D * 128.0))
#define INV_DPf ((float)(255.0 / (256.0 * SQRT2_D)))
#define DTf     ((float)(2.0 * SQRT2_D / 256.0))
#define PI_D    3.141592653589793

__device__ float4 g_pair4N[PW * PW]; // (A[y][x],B[y][x],A[y][x+1],B[y][x+1]) padded
__device__ float4 g_pair4T[PW * PW]; // transposed pairs
__device__ float2 g_img2 [HW];       // unpadded interleave (bwd final update)
__device__ float2 g_temp [V * D];    // residual sinogram rows v<96 (A,B)
__device__ float4 g_pair [V * D];    // (temp[j], temp[j+1]) x both images
__device__ float  g_colA [8 * 96 * 256];  // column partial sums, 8 row-groups
__device__ float  g_colB [8 * 96 * 256];
__device__ float4 g_trig4[96];       // {svDP, cvDP, svI, cvI} for bwd
__device__ float2 g_trigB[96];       // raw {cv, sv} for fwd2

// ---------------------------------------------------------------------------
// prep: build x-shifted pair images (normal + transposed) from a 17x17-halo
// smem tile, border-frame zeroing WITH correct col-1 pair elements, trig.
// Col 1 of the padded frame represents x=-1: first element is 0 (outside),
// but the baked x+1 element must be the true img[...][0] column.
// ---------------------------------------------------------------------------
__global__ void __launch_bounds__(256) prep_kernel(const float* __restrict__ img) {
    __shared__ float2 s[17][17];
    const int tid = threadIdx.x;
    const int tx = tid & 15, ty = tid >> 4;
    const int bx = (blockIdx.x & 15) << 4;
    const int by = (blockIdx.x >> 4) << 4;

    for (int i = tid; i < 289; i += 256) {
        int r = i / 17, c = i - r * 17;
        int y = by + r, x = bx + c;
        float2 val = make_float2(0.f, 0.f);
        if (x < W && y < H) val = make_float2(img[y * W + x], img[y * W + x + HW]);
        s[r][c] = val;
    }
    __syncthreads();

    {   // normal pair + unpadded interleave
        int x = bx + tx, y = by + ty;
        float2 v00 = s[ty][tx], v01 = s[ty][tx + 1];
        g_img2[y * W + x] = v00;
        g_pair4N[(y + 2) * PW + (x + 2)] = make_float4(v00.x, v00.y, v01.x, v01.y);
    }
    {   // transposed pair: out(row=x, col=y) = (img[y][x], img[y+1][x])
        float2 u0 = s[tx][ty], u1 = s[tx + 1][ty];
        g_pair4T[(bx + ty + 2) * PW + (by + tx + 2)] = make_float4(u0.x, u0.y, u1.x, u1.y);
    }

    // border frame: [0,259]^2 minus [2,257]^2 = 2064 cells per array.
    // All zero EXCEPT col 1 data rows, whose pair element is the edge column.
    if (blockIdx.x < 2) {
        const bool isN = (blockIdx.x == 0);
        float4* dst = isN ? g_pair4N : g_pair4T;
        for (int i = tid; i < 2064; i += 256) {
            int r, c;
            if (i < 1040) {                    // rows {0,1,258,259} x cols [0,259]
                int rr = i / 260;  c = i - rr * 260;
                r = (rr < 2) ? rr : (256 + rr);
            } else {                           // cols {0,1,258,259} x rows [2,257]
                int j = i - 1040;
                int cc = j / 256;  r = 2 + (j - cc * 256);
                c = (cc < 2) ? cc : (256 + cc);
            }
            float4 val = make_float4(0.f, 0.f, 0.f, 0.f);
            if (c == 1 && r >= 2 && r <= 257) {
                int t = r - 2;
                if (isN) {      // pairN[y][-1].zw = img[y][0]
                    val.z = img[t * W];
                    val.w = img[t * W + HW];
                } else {        // pairT[x][-1].zw = img[0][x]
                    val.z = img[t];
                    val.w = img[t + HW];
                }
            }
            dst[r * PW + c] = val;
        }
    }

    if (blockIdx.x < 96 && tid == 0) {
        const int v = blockIdx.x;
        float cv, sv;
        float af = (float)((double)v * (PI_D / 192.0));
        sincosf(af, &sv, &cv);
        g_trigB[v] = make_float2(cv, sv);
        g_trig4[v] = make_float4(sv * DPf, cv * DPf, sv * INV_DPf, cv * INV_DPf);
    }
}

// ---------------------------------------------------------------------------
// fwd2: sample field F_v[j][k] for base angles v<96 serves BOTH sinogram
// halves (90-degree identity). Warp-per-row (lanes along k). Pair images:
// 2 LDG.128 per bilinear sample.
// ---------------------------------------------------------------------------
__global__ void __launch_bounds__(256) fwd2_kernel(const float* __restrict__ proj) {
    __shared__ float2 shW[8][256];               // per-warp column partials
    const int bid = blockIdx.x;
    const int v   = bid >> 3;
    const int grp = bid & 7;
    const int tid = threadIdx.x;
    const int warp = tid >> 5, lane = tid & 31;

    const float2 tv = g_trigB[v];
    const float cv = tv.x, sv = tv.y;
    const bool steep = fabsf(sv) > fabsf(cv);
    const float4* __restrict__ im4 = steep ? g_pair4T : g_pair4N;
    const float c2 = steep ? sv : cv;
    const float s2 = steep ? cv : sv;

    float cA[8], cB[8];
    #pragma unroll
    for (int c = 0; c < 8; ++c) { cA[c] = 0.f; cB[c] = 0.f; }

    #pragma unroll 1
    for (int r = 0; r < 4; ++r) {
        const int j = (grp << 5) + (r << 3) + warp;
        const float s128 = fmaf((float)j, DPf, OFFf);
        const float ax0 = fmaf(-s128, sv, 129.5f);   // padded (+2)
        const float ay0 = fmaf( s128, cv, 129.5f);
        const float aX = steep ? ay0 : ax0;
        const float aY = steep ? ax0 : ay0;
        const float bX = fmaf(OFFf, c2, aX), sX = DPf * c2;   // X(k) = bX + k*sX
        const float bY = fmaf(OFFf, s2, aY), sY = DPf * s2;

        float lo = 0.f, hi = 255.f;
        bool empty = false;
        {
            float rr = 1.0f / sX;
            float t1 = (0.999f - bX) * rr, t2 = (258.001f - bX) * rr;
            lo = fmaxf(lo, fminf(t1, t2)); hi = fminf(hi, fmaxf(t1, t2));
        }
        if (fabsf(sY) > 1e-6f) {
            float rr = 1.0f / sY;
            float t1 = (0.999f - bY) * rr, t2 = (258.001f - bY) * rr;
            lo = fmaxf(lo, fminf(t1, t2)); hi = fminf(hi, fmaxf(t1, t2));
        } else if (bY < 0.999f || bY > 258.001f) empty = true;

        int klo = (int)ceilf(lo), khi = (int)floorf(hi);
        float rowA = 0.f, rowB = 0.f;
        if (!empty && klo <= khi) {
            const int c0 = klo >> 5, c1 = khi >> 5;
            #pragma unroll
            for (int c = 0; c < 8; ++c) {
                if (c >= c0 && c <= c1) {           // warp-uniform branch
                    const int k = (c << 5) + lane;
                    const float pred = (k >= klo && k <= khi) ? 1.f : 0.f;
                    float X = fmaf((float)k, sX, bX);
                    float Y = fmaf((float)k, sY, bY);
                    X = fminf(fmaxf(X, 0.f), 258.f);   // safe for pred=0 lanes
                    Y = fminf(fmaxf(Y, 0.f), 258.f);
                    float Xf = floorf(X), Yf = floorf(Y);
                    float fx = X - Xf, fy = Y - Yf;
                    int base = (int)Yf * PW + (int)Xf;
                    float4 t0 = __ldg(im4 + base);        // (A00,B00,A10,B10)
                    float4 t1 = __ldg(im4 + base + PW);   // (A01,B01,A11,B11)
                    float gx = 1.f - fx, gy = 1.f - fy;
                    float w00 = gx * gy, w10 = fx * gy, w01 = gx * fy, w11 = fx * fy;
                    float fa = fmaf(t0.x, w00, fmaf(t0.z, w10, fmaf(t1.x, w01, t1.z * w11)));
                    float fb = fmaf(t0.y, w00, fmaf(t0.w, w10, fmaf(t1.y, w01, t1.w * w11)));
                    fa *= pred; fb *= pred;
                    rowA += fa;  rowB += fb;
                    cA[c] += fa; cB[c] += fb;
                }
            }
        }
        #pragma unroll
        for (int o = 16; o; o >>= 1) {
            rowA += __shfl_xor_sync(0xffffffffu, rowA, o);
            rowB += __shfl_xor_sync(0xffffffffu, rowB, o);
        }
        if (lane == 0) {
            int idx = v * D + j;
            g_temp[idx] = make_float2(fmaf(DTf, rowA, -__ldg(proj + idx)),
                                      fmaf(DTf, rowB, -__ldg(proj + idx + V * D)));
        }
    }

    // deterministic column reduction: warp slices -> smem -> fixed-order sum
    #pragma unroll
    for (int c = 0; c < 8; ++c)
        shW[warp][(c << 5) + lane] = make_float2(cA[c], cB[c]);
    __syncthreads();
    float a = 0.f, b = 0.f;
    #pragma unroll
    for (int w = 0; w < 8; ++w) {
        float2 t = shW[w][tid];
        a += t.x; b += t.y;
    }
    g_colA[((grp * 96 + v) << 8) + tid] = a;
    g_colB[((grp * 96 + v) << 8) + tid] = b;
}

// ---------------------------------------------------------------------------
// combine: finalize sinogram rows v>=96 (fixed-order, deterministic) and
// build the float4 pair array (t[j], t[j+1]) for bwd.
// ---------------------------------------------------------------------------
__global__ void __launch_bounds__(256) combine_kernel(const float* __restrict__ proj) {
    __shared__ float2 sval[256];
    const int v = blockIdx.x;          // 0..191
    const int j = threadIdx.x;
    float2 val;
    if (v < 96) {
        val = g_temp[v * D + j];
    } else {
        const int vb = v - 96;
        const int kk = 255 - j;
        float a = 0.f, b = 0.f;
        #pragma unroll
        for (int g = 0; g < 8; ++g) {
            a += g_colA[((g * 96 + vb) << 8) + kk];
            b += g_colB[((g * 96 + vb) << 8) + kk];
        }
        int idx = v * D + j;
        val = make_float2(fmaf(DTf, a, -__ldg(proj + idx)),
                          fmaf(DTf, b, -__ldg(proj + idx + V * D)));
    }
    sval[j] = val;
    __syncthreads();
    float2 nxt = sval[min(j + 1, 255)];
    g_pair[(v << 8) + j] = make_float4(val.x, val.y, nxt.x, nxt.y);
}

// ---------------------------------------------------------------------------
// backprojection + update. 512-thread blocks: 4 angle-slices x 128 pixels;
// fixed-order smem combine (deterministic). unroll 4 for deeper LDG overlap.
// ---------------------------------------------------------------------------
__global__ void __launch_bounds__(512) bwd_kernel(const float* __restrict__ wptr,
                                                  float* __restrict__ out) {
    __shared__ float4 sg[96];
    __shared__ float2 spart[3][128];
    const int tid = threadIdx.x;
    if (tid < 96) sg[tid] = g_trig4[tid];
    __syncthreads();

    const int pxi   = tid & 127;
    const int slice = tid >> 7;              // 0..3
    const int p  = blockIdx.x * 128 + pxi;
    const int ix = p & (W - 1);
    const int iy = p >> 8;
    const float px = (float)ix - 127.5f;
    const float py = (float)iy - 127.5f;
    const float npx = -px;

    float accA0 = 0.f, accB0 = 0.f, accA1 = 0.f, accB1 = 0.f;
    const int v0 = slice * 24;
    const float4* __restrict__ row  = g_pair + v0 * D;          // angle v
    const float4* __restrict__ rowm = g_pair + (96 + v0) * D;   // angle v+96

    #pragma unroll 4
    for (int v = v0; v < v0 + 24; ++v, row += D, rowm += D) {
        const float4 q = sg[v];
        const float svDP = q.x, cvDP = q.y, svI = q.z, cvI = q.w;

        const float jc = fmaf(py, cvI, fmaf(npx, svI, 127.5f));
        const float kc = fmaf(px, cvI, fmaf(py,  svI, 127.5f));
        const float jf = floorf(jc), kf = floorf(kc);
        const float fj = jc - jf,    fk = kc - kf;
        const int   j0 = (int)jf;
        const int   k0 = (int)kf;

        const float dx00 = fmaf(fj, svDP, -(fk * cvDP));
        const float u    = fmaf(fj, cvDP,  (fk * svDP));
        const float dx10 = dx00 - svDP;
        const float dx01 = dx00 + cvDP;
        const float dx11 = dx10 + cvDP;
        const float e10  = u - cvDP;
        const float e01  = u - svDP;
        const float e11  = e10 - svDP;

        const float hx00 = __saturatef(1.f - fabsf(dx00));
        const float hx10 = __saturatef(1.f - fabsf(dx10));
        const float hx01 = __saturatef(1.f - fabsf(dx01));
        const float hx11 = __saturatef(1.f - fabsf(dx11));
        const float hy00 = __saturatef(1.f - fabsf(u));
        const float hy10 = __saturatef(1.f - fabsf(e10));
        const float hy01 = __saturatef(1.f - fabsf(e01));
        const float hy11 = __saturatef(1.f - fabsf(e11));

        const float P00 = hx00 * hy00;
        const float P10 = hx10 * hy10;
        const float P01 = hx01 * hy01;
        const float P11 = hx11 * hy11;

        const float q0 = P00 + P01, q1 = P10 + P11;   // angle v
        const float r0 = P01 + P11, r1 = P00 + P10;   // angle v+96

        const float4 t01 = __ldg(row + j0);
        const float4 m01 = __ldg(rowm + (254 - k0));
        accA0 = fmaf(t01.x, q0, fmaf(t01.z, q1, accA0));
        accB0 = fmaf(t01.y, q0, fmaf(t01.w, q1, accB0));
        accA1 = fmaf(m01.x, r0, fmaf(m01.z, r1, accA1));
        accB1 = fmaf(m01.y, r0, fmaf(m01.w, r1, accB1));
    }

    const float accA = accA0 + accA1;
    const float accB = accB0 + accB1;
    if (slice != 0) spart[slice - 1][pxi] = make_float2(accA, accB);
    __syncthreads();
    if (slice == 0) {
        float a = accA, b = accB;
        #pragma unroll
        for (int s = 0; s < 3; ++s) {       // fixed order -> deterministic
            float2 t = spart[s][pxi];
            a += t.x; b += t.y;
        }
        const float wdt = __ldg(wptr) * DTf;
        const float2 ia = g_img2[p];
        out[p]      = fmaf(-wdt, a, ia.x);
        out[p + HW] = fmaf(-wdt, b, ia.y);
    }
}

// ---------------------------------------------------------------------------
extern "C" void kernel_launch(void* const* d_in, const int* in_sizes, int n_in,
                              void* d_out, int out_size) {
    const float* img  = (const float*)d_in[0];   // [2,1,256,256]
    const float* proj = (const float*)d_in[1];   // [2,1,192,256]
    const float* wptr = (const float*)d_in[2];   // [1]
    float* out = (float*)d_out;                  // [2,1,256,256]

    prep_kernel<<<256, 256>>>(img);
    fwd2_kernel<<<768, 256>>>(proj);
    combine_kernel<<<192, 256>>>(proj);
    bwd_kernel<<<HW / 128, 512>>>(wptr, out);
}

// round 13
// speedup vs baseline: 1.0375x; 1.0375x over previous
#include <cuda_runtime.h>
#include <math.h>

#define H 256
#define W 256
#define V 192
#define D 256
#define S 256
#define HW (H*W)
#define PW 264              /* padded stride: data at [2,257], frame zeros [0,259] */

#define SQRT2_D 1.4142135623730951
#define DPf     ((float)(2.0 * SQRT2_D * 128.0 / 255.0))   /* sample spacing, px */
#define OFFf    ((float)(-SQRT2_D * 128.0))
#define INV_DPf ((float)(255.0 / (256.0 * SQRT2_D)))
#define DTf     ((float)(2.0 * SQRT2_D / 256.0))
#define PI_D    3.141592653589793

__device__ float4 g_pair4N[PW * PW]; // (A[y][x],B[y][x],A[y][x+1],B[y][x+1]) padded
__device__ float4 g_pair4T[PW * PW]; // transposed pairs
__device__ float2 g_img2 [HW];       // unpadded interleave (bwd final update)
__device__ float2 g_temp [V * D];    // residual sinogram rows v<96 (A,B)
__device__ float4 g_pair [V * D];    // (temp[j], temp[j+1]) x both images
__device__ float  g_colA [8 * 96 * 256];  // column partial sums, 8 row-groups
__device__ float  g_colB [8 * 96 * 256];
__device__ float4 g_trig4[96];       // {svDP, cvDP, svI, cvI} for bwd
__device__ float2 g_trigB[96];       // raw {cv, sv} for fwd2

// ---------------------------------------------------------------------------
// prep: build x-shifted pair images (normal + transposed) from a 17x17-halo
// smem tile, border-frame zeroing WITH correct col-1 pair elements, trig.
// Col 1 of the padded frame represents x=-1: first element is 0 (outside),
// but the baked x+1 element must be the true img[...][0] column.
// ---------------------------------------------------------------------------
__global__ void __launch_bounds__(256) prep_kernel(const float* __restrict__ img) {
    __shared__ float2 s[17][17];
    const int tid = threadIdx.x;
    const int tx = tid & 15, ty = tid >> 4;
    const int bx = (blockIdx.x & 15) << 4;
    const int by = (blockIdx.x >> 4) << 4;

    for (int i = tid; i < 289; i += 256) {
        int r = i / 17, c = i - r * 17;
        int y = by + r, x = bx + c;
        float2 val = make_float2(0.f, 0.f);
        if (x < W && y < H) val = make_float2(img[y * W + x], img[y * W + x + HW]);
        s[r][c] = val;
    }
    __syncthreads();

    {   // normal pair + unpadded interleave
        int x = bx + tx, y = by + ty;
        float2 v00 = s[ty][tx], v01 = s[ty][tx + 1];
        g_img2[y * W + x] = v00;
        g_pair4N[(y + 2) * PW + (x + 2)] = make_float4(v00.x, v00.y, v01.x, v01.y);
    }
    {   // transposed pair: out(row=x, col=y) = (img[y][x], img[y+1][x])
        float2 u0 = s[tx][ty], u1 = s[tx + 1][ty];
        g_pair4T[(bx + ty + 2) * PW + (by + tx + 2)] = make_float4(u0.x, u0.y, u1.x, u1.y);
    }

    // border frame: [0,259]^2 minus [2,257]^2 = 2064 cells per array.
    // All zero EXCEPT col 1 data rows, whose pair element is the edge column.
    if (blockIdx.x < 2) {
        const bool isN = (blockIdx.x == 0);
        float4* dst = isN ? g_pair4N : g_pair4T;
        for (int i = tid; i < 2064; i += 256) {
            int r, c;
            if (i < 1040) {                    // rows {0,1,258,259} x cols [0,259]
                int rr = i / 260;  c = i - rr * 260;
                r = (rr < 2) ? rr : (256 + rr);
            } else {                           // cols {0,1,258,259} x rows [2,257]
                int j = i - 1040;
                int cc = j / 256;  r = 2 + (j - cc * 256);
                c = (cc < 2) ? cc : (256 + cc);
            }
            float4 val = make_float4(0.f, 0.f, 0.f, 0.f);
            if (c == 1 && r >= 2 && r <= 257) {
                int t = r - 2;
                if (isN) {      // pairN[y][-1].zw = img[y][0]
                    val.z = img[t * W];
                    val.w = img[t * W + HW];
                } else {        // pairT[x][-1].zw = img[0][x]
                    val.z = img[t];
                    val.w = img[t + HW];
                }
            }
            dst[r * PW + c] = val;
        }
    }

    if (blockIdx.x < 96 && tid == 0) {
        const int v = blockIdx.x;
        float cv, sv;
        float af = (float)((double)v * (PI_D / 192.0));
        sincosf(af, &sv, &cv);
        g_trigB[v] = make_float2(cv, sv);
        g_trig4[v] = make_float4(sv * DPf, cv * DPf, sv * INV_DPf, cv * INV_DPf);
    }
}

// ---------------------------------------------------------------------------
// fwd2: sample field F_v[j][k] for base angles v<96 serves BOTH sinogram
// halves (90-degree identity). Warp-per-row (lanes along k). Pair images:
// 2 LDG.128 per bilinear sample.
// ---------------------------------------------------------------------------
__global__ void __launch_bounds__(256) fwd2_kernel(const float* __restrict__ proj) {
    __shared__ float2 shW[8][256];               // per-warp column partials
    const int bid = blockIdx.x;
    const int v   = bid >> 3;
    const int grp = bid & 7;
    const int tid = threadIdx.x;
    const int warp = tid >> 5, lane = tid & 31;

    const float2 tv = g_trigB[v];
    const float cv = tv.x, sv = tv.y;
    const bool steep = fabsf(sv) > fabsf(cv);
    const float4* __restrict__ im4 = steep ? g_pair4T : g_pair4N;
    const float c2 = steep ? sv : cv;
    const float s2 = steep ? cv : sv;

    float cA[8], cB[8];
    #pragma unroll
    for (int c = 0; c < 8; ++c) { cA[c] = 0.f; cB[c] = 0.f; }

    #pragma unroll 1
    for (int r = 0; r < 4; ++r) {
        const int j = (grp << 5) + (r << 3) + warp;
        const float s128 = fmaf((float)j, DPf, OFFf);
        const float ax0 = fmaf(-s128, sv, 129.5f);   // padded (+2)
        const float ay0 = fmaf( s128, cv, 129.5f);
        const float aX = steep ? ay0 : ax0;
        const float aY = steep ? ax0 : ay0;
        const float bX = fmaf(OFFf, c2, aX), sX = DPf * c2;   // X(k) = bX + k*sX
        const float bY = fmaf(OFFf, s2, aY), sY = DPf * s2;

        float lo = 0.f, hi = 255.f;
        bool empty = false;
        {
            float rr = 1.0f / sX;
            float t1 = (0.999f - bX) * rr, t2 = (258.001f - bX) * rr;
            lo = fmaxf(lo, fminf(t1, t2)); hi = fminf(hi, fmaxf(t1, t2));
        }
        if (fabsf(sY) > 1e-6f) {
            float rr = 1.0f / sY;
            float t1 = (0.999f - bY) * rr, t2 = (258.001f - bY) * rr;
            lo = fmaxf(lo, fminf(t1, t2)); hi = fminf(hi, fmaxf(t1, t2));
        } else if (bY < 0.999f || bY > 258.001f) empty = true;

        int klo = (int)ceilf(lo), khi = (int)floorf(hi);
        float rowA = 0.f, rowB = 0.f;
        if (!empty && klo <= khi) {
            const int c0 = klo >> 5, c1 = khi >> 5;
            #pragma unroll
            for (int c = 0; c < 8; ++c) {
                if (c >= c0 && c <= c1) {           // warp-uniform branch
                    const int k = (c << 5) + lane;
                    const float pred = (k >= klo && k <= khi) ? 1.f : 0.f;
                    float X = fmaf((float)k, sX, bX);
                    float Y = fmaf((float)k, sY, bY);
                    X = fminf(fmaxf(X, 0.f), 258.f);   // safe for pred=0 lanes
                    Y = fminf(fmaxf(Y, 0.f), 258.f);
                    float Xf = floorf(X), Yf = floorf(Y);
                    float fx = X - Xf, fy = Y - Yf;
                    int base = (int)Yf * PW + (int)Xf;
                    float4 t0 = __ldg(im4 + base);        // (A00,B00,A10,B10)
                    float4 t1 = __ldg(im4 + base + PW);   // (A01,B01,A11,B11)
                    float gx = 1.f - fx, gy = 1.f - fy;
                    float w00 = gx * gy, w10 = fx * gy, w01 = gx * fy, w11 = fx * fy;
                    float fa = fmaf(t0.x, w00, fmaf(t0.z, w10, fmaf(t1.x, w01, t1.z * w11)));
                    float fb = fmaf(t0.y, w00, fmaf(t0.w, w10, fmaf(t1.y, w01, t1.w * w11)));
                    fa *= pred; fb *= pred;
                    rowA += fa;  rowB += fb;
                    cA[c] += fa; cB[c] += fb;
                }
            }
        }
        #pragma unroll
        for (int o = 16; o; o >>= 1) {
            rowA += __shfl_xor_sync(0xffffffffu, rowA, o);
            rowB += __shfl_xor_sync(0xffffffffu, rowB, o);
        }
        if (lane == 0) {
            int idx = v * D + j;
            g_temp[idx] = make_float2(fmaf(DTf, rowA, -__ldg(proj + idx)),
                                      fmaf(DTf, rowB, -__ldg(proj + idx + V * D)));
        }
    }

    // deterministic column reduction: warp slices -> smem -> fixed-order sum
    #pragma unroll
    for (int c = 0; c < 8; ++c)
        shW[warp][(c << 5) + lane] = make_float2(cA[c], cB[c]);
    __syncthreads();
    float a = 0.f, b = 0.f;
    #pragma unroll
    for (int w = 0; w < 8; ++w) {
        float2 t = shW[w][tid];
        a += t.x; b += t.y;
    }
    g_colA[((grp * 96 + v) << 8) + tid] = a;
    g_colB[((grp * 96 + v) << 8) + tid] = b;
}

// ---------------------------------------------------------------------------
// combine: finalize sinogram rows v>=96 (fixed-order, deterministic) and
// build the float4 pair array (t[j], t[j+1]) for bwd.
// ---------------------------------------------------------------------------
__global__ void __launch_bounds__(256) combine_kernel(const float* __restrict__ proj) {
    __shared__ float2 sval[256];
    const int v = blockIdx.x;          // 0..191
    const int j = threadIdx.x;
    float2 val;
    if (v < 96) {
        val = g_temp[v * D + j];
    } else {
        const int vb = v - 96;
        const int kk = 255 - j;
        float a = 0.f, b = 0.f;
        #pragma unroll
        for (int g = 0; g < 8; ++g) {
            a += g_colA[((g * 96 + vb) << 8) + kk];
            b += g_colB[((g * 96 + vb) << 8) + kk];
        }
        int idx = v * D + j;
        val = make_float2(fmaf(DTf, a, -__ldg(proj + idx)),
                          fmaf(DTf, b, -__ldg(proj + idx + V * D)));
    }
    sval[j] = val;
    __syncthreads();
    float2 nxt = sval[min(j + 1, 255)];
    g_pair[(v << 8) + j] = make_float4(val.x, val.y, nxt.x, nxt.y);
}

// ---------------------------------------------------------------------------
// backprojection + update. 512-thread blocks: 4 angle-slices x 128 pixels;
// fixed-order smem combine (deterministic). unroll 2 = best measured config
// (regs 32, occ 80%). Epilogue loads hoisted above the combine barrier.
// ---------------------------------------------------------------------------
__global__ void __launch_bounds__(512) bwd_kernel(const float* __restrict__ wptr,
                                                  float* __restrict__ out) {
    __shared__ float4 sg[96];
    __shared__ float2 spart[3][128];
    const int tid = threadIdx.x;
    if (tid < 96) sg[tid] = g_trig4[tid];
    __syncthreads();

    const int pxi   = tid & 127;
    const int slice = tid >> 7;              // 0..3
    const int p  = blockIdx.x * 128 + pxi;
    const int ix = p & (W - 1);
    const int iy = p >> 8;
    const float px = (float)ix - 127.5f;
    const float py = (float)iy - 127.5f;
    const float npx = -px;

    float accA0 = 0.f, accB0 = 0.f, accA1 = 0.f, accB1 = 0.f;
    const int v0 = slice * 24;
    const float4* __restrict__ row  = g_pair + v0 * D;          // angle v
    const float4* __restrict__ rowm = g_pair + (96 + v0) * D;   // angle v+96

    #pragma unroll 2
    for (int v = v0; v < v0 + 24; ++v, row += D, rowm += D) {
        const float4 q = sg[v];
        const float svDP = q.x, cvDP = q.y, svI = q.z, cvI = q.w;

        const float jc = fmaf(py, cvI, fmaf(npx, svI, 127.5f));
        const float kc = fmaf(px, cvI, fmaf(py,  svI, 127.5f));
        const float jf = floorf(jc), kf = floorf(kc);
        const float fj = jc - jf,    fk = kc - kf;
        const int   j0 = (int)jf;
        const int   k0 = (int)kf;

        const float dx00 = fmaf(fj, svDP, -(fk * cvDP));
        const float u    = fmaf(fj, cvDP,  (fk * svDP));
        const float dx10 = dx00 - svDP;
        const float dx01 = dx00 + cvDP;
        const float dx11 = dx10 + cvDP;
        const float e10  = u - cvDP;
        const float e01  = u - svDP;
        const float e11  = e10 - svDP;

        const float hx00 = __saturatef(1.f - fabsf(dx00));
        const float hx10 = __saturatef(1.f - fabsf(dx10));
        const float hx01 = __saturatef(1.f - fabsf(dx01));
        const float hx11 = __saturatef(1.f - fabsf(dx11));
        const float hy00 = __saturatef(1.f - fabsf(u));
        const float hy10 = __saturatef(1.f - fabsf(e10));
        const float hy01 = __saturatef(1.f - fabsf(e01));
        const float hy11 = __saturatef(1.f - fabsf(e11));

        const float P00 = hx00 * hy00;
        const float P10 = hx10 * hy10;
        const float P01 = hx01 * hy01;
        const float P11 = hx11 * hy11;

        const float q0 = P00 + P01, q1 = P10 + P11;   // angle v
        const float r0 = P01 + P11, r1 = P00 + P10;   // angle v+96

        const float4 t01 = __ldg(row + j0);
        const float4 m01 = __ldg(rowm + (254 - k0));
        accA0 = fmaf(t01.x, q0, fmaf(t01.z, q1, accA0));
        accB0 = fmaf(t01.y, q0, fmaf(t01.w, q1, accB0));
        accA1 = fmaf(m01.x, r0, fmaf(m01.z, r1, accA1));
        accB1 = fmaf(m01.y, r0, fmaf(m01.w, r1, accB1));
    }

    const float accA = accA0 + accA1;
    const float accB = accB0 + accB1;
    // hoist epilogue loads above the barrier so they overlap the wait
    float wdt = 0.f; float2 ia = make_float2(0.f, 0.f);
    if (slice == 0) { wdt = __ldg(wptr) * DTf; ia = g_img2[p]; }
    if (slice != 0) spart[slice - 1][pxi] = make_float2(accA, accB);
    __syncthreads();
    if (slice == 0) {
        float a = accA, b = accB;
        #pragma unroll
        for (int s = 0; s < 3; ++s) {       // fixed order -> deterministic
            float2 t = spart[s][pxi];
            a += t.x; b += t.y;
        }
        out[p]      = fmaf(-wdt, a, ia.x);
        out[p + HW] = fmaf(-wdt, b, ia.y);
    }
}

// ---------------------------------------------------------------------------
extern "C" void kernel_launch(void* const* d_in, const int* in_sizes, int n_in,
                              void* d_out, int out_size) {
    const float* img  = (const float*)d_in[0];   // [2,1,256,256]
    const float* proj = (const float*)d_in[1];   // [2,1,192,256]
    const float* wptr = (const float*)d_in[2];   // [1]
    float* out = (float*)d_out;                  // [2,1,256,256]

    prep_kernel<<<256, 256>>>(img);
    fwd2_kernel<<<768, 256>>>(proj);
    combine_kernel<<<192, 256>>>(proj);
    bwd_kernel<<<HW / 128, 512>>>(wptr, out);
}

// round 15
// speedup vs baseline: 1.1000x; 1.0603x over previous
#include <cuda_runtime.h>
#include <math.h>

#define H 256
#define W 256
#define V 192
#define D 256
#define S 256
#define HW (H*W)
#define PW 264              /* padded stride: data at [2,257], frame zeros [0,259] */

#define SQRT2_D 1.4142135623730951
#define DPf     ((float)(2.0 * SQRT2_D * 128.0 / 255.0))   /* sample spacing, px */
#define OFFf    ((float)(-SQRT2_D * 128.0))
#define INV_DPf ((float)(255.0 / (256.0 * SQRT2_D)))
#define DTf     ((float)(2.0 * SQRT2_D / 256.0))
#define PI_D    3.141592653589793

__device__ float4 g_pair4N[PW * PW]; // (A[y][x],B[y][x],A[y][x+1],B[y][x+1]) padded
__device__ float4 g_pair4T[PW * PW]; // transposed pairs
__device__ float2 g_img2 [HW];       // unpadded interleave (bwd final update)
__device__ float2 g_temp [V * D];    // residual sinogram rows v<96 (A,B)
__device__ float4 g_pair [V * D];    // (temp[j], temp[j+1]) x both images
__device__ float  g_colA [8 * 96 * 256];  // column partial sums, 8 row-groups
__device__ float  g_colB [8 * 96 * 256];
__device__ float4 g_trig4[96];       // {svDP, cvDP, svI, cvI} for bwd
__device__ float2 g_trigB[96];       // raw {cv, sv} for fwd2

// ---------------------------------------------------------------------------
// prep: build x-shifted pair images (normal + transposed) from a 17x17-halo
// smem tile, border-frame zeroing WITH correct col-1 pair elements, trig.
// ---------------------------------------------------------------------------
__global__ void __launch_bounds__(256) prep_kernel(const float* __restrict__ img) {
    __shared__ float2 s[17][17];
    const int tid = threadIdx.x;
    const int tx = tid & 15, ty = tid >> 4;
    const int bx = (blockIdx.x & 15) << 4;
    const int by = (blockIdx.x >> 4) << 4;

    for (int i = tid; i < 289; i += 256) {
        int r = i / 17, c = i - r * 17;
        int y = by + r, x = bx + c;
        float2 val = make_float2(0.f, 0.f);
        if (x < W && y < H) val = make_float2(img[y * W + x], img[y * W + x + HW]);
        s[r][c] = val;
    }
    __syncthreads();

    {   // normal pair + unpadded interleave
        int x = bx + tx, y = by + ty;
        float2 v00 = s[ty][tx], v01 = s[ty][tx + 1];
        g_img2[y * W + x] = v00;
        g_pair4N[(y + 2) * PW + (x + 2)] = make_float4(v00.x, v00.y, v01.x, v01.y);
    }
    {   // transposed pair: out(row=x, col=y) = (img[y][x], img[y+1][x])
        float2 u0 = s[tx][ty], u1 = s[tx + 1][ty];
        g_pair4T[(bx + ty + 2) * PW + (by + tx + 2)] = make_float4(u0.x, u0.y, u1.x, u1.y);
    }

    // border frame: all zero EXCEPT col 1 data rows (pair elem = edge column)
    if (blockIdx.x < 2) {
        const bool isN = (blockIdx.x == 0);
        float4* dst = isN ? g_pair4N : g_pair4T;
        for (int i = tid; i < 2064; i += 256) {
            int r, c;
            if (i < 1040) {                    // rows {0,1,258,259} x cols [0,259]
                int rr = i / 260;  c = i - rr * 260;
                r = (rr < 2) ? rr : (256 + rr);
            } else {                           // cols {0,1,258,259} x rows [2,257]
                int j = i - 1040;
                int cc = j / 256;  r = 2 + (j - cc * 256);
                c = (cc < 2) ? cc : (256 + cc);
            }
            float4 val = make_float4(0.f, 0.f, 0.f, 0.f);
            if (c == 1 && r >= 2 && r <= 257) {
                int t = r - 2;
                if (isN) { val.z = img[t * W]; val.w = img[t * W + HW]; }
                else     { val.z = img[t];     val.w = img[t + HW]; }
            }
            dst[r * PW + c] = val;
        }
    }

    if (blockIdx.x < 96 && tid == 0) {
        const int v = blockIdx.x;
        float cv, sv;
        float af = (float)((double)v * (PI_D / 192.0));
        sincosf(af, &sv, &cv);
        g_trigB[v] = make_float2(cv, sv);
        g_trig4[v] = make_float4(sv * DPf, cv * DPf, sv * INV_DPf, cv * INV_DPf);
    }
}

// ---------------------------------------------------------------------------
// fwd2: sample field F_v[j][k] for base angles v<96 serves BOTH sinogram
// halves (90-degree identity). Warp-per-row (lanes along k). Pair images:
// 2 LDG.128 per bilinear sample.
// ---------------------------------------------------------------------------
__global__ void __launch_bounds__(256) fwd2_kernel(const float* __restrict__ proj) {
    __shared__ float2 shW[8][256];               // per-warp column partials
    const int bid = blockIdx.x;
    const int v   = bid >> 3;
    const int grp = bid & 7;
    const int tid = threadIdx.x;
    const int warp = tid >> 5, lane = tid & 31;

    const float2 tv = g_trigB[v];
    const float cv = tv.x, sv = tv.y;
    const bool steep = fabsf(sv) > fabsf(cv);
    const float4* __restrict__ im4 = steep ? g_pair4T : g_pair4N;
    const float c2 = steep ? sv : cv;
    const float s2 = steep ? cv : sv;

    float cA[8], cB[8];
    #pragma unroll
    for (int c = 0; c < 8; ++c) { cA[c] = 0.f; cB[c] = 0.f; }

    #pragma unroll 1
    for (int r = 0; r < 4; ++r) {
        const int j = (grp << 5) + (r << 3) + warp;
        const float s128 = fmaf((float)j, DPf, OFFf);
        const float ax0 = fmaf(-s128, sv, 129.5f);   // padded (+2)
        const float ay0 = fmaf( s128, cv, 129.5f);
        const float aX = steep ? ay0 : ax0;
        const float aY = steep ? ax0 : ay0;
        const float bX = fmaf(OFFf, c2, aX), sX = DPf * c2;   // X(k) = bX + k*sX
        const float bY = fmaf(OFFf, s2, aY), sY = DPf * s2;

        float lo = 0.f, hi = 255.f;
        bool empty = false;
        {
            float rr = 1.0f / sX;
            float t1 = (0.999f - bX) * rr, t2 = (258.001f - bX) * rr;
            lo = fmaxf(lo, fminf(t1, t2)); hi = fminf(hi, fmaxf(t1, t2));
        }
        if (fabsf(sY) > 1e-6f) {
            float rr = 1.0f / sY;
            float t1 = (0.999f - bY) * rr, t2 = (258.001f - bY) * rr;
            lo = fmaxf(lo, fminf(t1, t2)); hi = fminf(hi, fmaxf(t1, t2));
        } else if (bY < 0.999f || bY > 258.001f) empty = true;

        int klo = (int)ceilf(lo), khi = (int)floorf(hi);
        float rowA = 0.f, rowB = 0.f;
        if (!empty && klo <= khi) {
            const int c0 = klo >> 5, c1 = khi >> 5;
            #pragma unroll
            for (int c = 0; c < 8; ++c) {
                if (c >= c0 && c <= c1) {           // warp-uniform branch
                    const int k = (c << 5) + lane;
                    const float pred = (k >= klo && k <= khi) ? 1.f : 0.f;
                    float X = fmaf((float)k, sX, bX);
                    float Y = fmaf((float)k, sY, bY);
                    X = fminf(fmaxf(X, 0.f), 258.f);   // safe for pred=0 lanes
                    Y = fminf(fmaxf(Y, 0.f), 258.f);
                    float Xf = floorf(X), Yf = floorf(Y);
                    float fx = X - Xf, fy = Y - Yf;
                    int base = (int)Yf * PW + (int)Xf;
                    float4 t0 = __ldg(im4 + base);        // (A00,B00,A10,B10)
                    float4 t1 = __ldg(im4 + base + PW);   // (A01,B01,A11,B11)
                    float gx = 1.f - fx, gy = 1.f - fy;
                    float w00 = gx * gy, w10 = fx * gy, w01 = gx * fy, w11 = fx * fy;
                    float fa = fmaf(t0.x, w00, fmaf(t0.z, w10, fmaf(t1.x, w01, t1.z * w11)));
                    float fb = fmaf(t0.y, w00, fmaf(t0.w, w10, fmaf(t1.y, w01, t1.w * w11)));
                    fa *= pred; fb *= pred;
                    rowA += fa;  rowB += fb;
                    cA[c] += fa; cB[c] += fb;
                }
            }
        }
        #pragma unroll
        for (int o = 16; o; o >>= 1) {
            rowA += __shfl_xor_sync(0xffffffffu, rowA, o);
            rowB += __shfl_xor_sync(0xffffffffu, rowB, o);
        }
        if (lane == 0) {
            int idx = v * D + j;
            g_temp[idx] = make_float2(fmaf(DTf, rowA, -__ldg(proj + idx)),
                                      fmaf(DTf, rowB, -__ldg(proj + idx + V * D)));
        }
    }

    // deterministic column reduction: warp slices -> smem -> fixed-order sum
    #pragma unroll
    for (int c = 0; c < 8; ++c)
        shW[warp][(c << 5) + lane] = make_float2(cA[c], cB[c]);
    __syncthreads();
    float a = 0.f, b = 0.f;
    #pragma unroll
    for (int w = 0; w < 8; ++w) {
        float2 t = shW[w][tid];
        a += t.x; b += t.y;
    }
    g_colA[((grp * 96 + v) << 8) + tid] = a;
    g_colB[((grp * 96 + v) << 8) + tid] = b;
}

// ---------------------------------------------------------------------------
// combine: finalize sinogram rows v>=96 (fixed-order, deterministic) and
// build the float4 pair array (t[j], t[j+1]) for bwd.
// ---------------------------------------------------------------------------
__global__ void __launch_bounds__(256) combine_kernel(const float* __restrict__ proj) {
    __shared__ float2 sval[256];
    const int v = blockIdx.x;          // 0..191
    const int j = threadIdx.x;
    float2 val;
    if (v < 96) {
        val = g_temp[v * D + j];
    } else {
        const int vb = v - 96;
        const int kk = 255 - j;
        float a = 0.f, b = 0.f;
        #pragma unroll
        for (int g = 0; g < 8; ++g) {
            a += g_colA[((g * 96 + vb) << 8) + kk];
            b += g_colB[((g * 96 + vb) << 8) + kk];
        }
        int idx = v * D + j;
        val = make_float2(fmaf(DTf, a, -__ldg(proj + idx)),
                          fmaf(DTf, b, -__ldg(proj + idx + V * D)));
    }
    sval[j] = val;
    __syncthreads();
    float2 nxt = sval[min(j + 1, 255)];
    g_pair[(v << 8) + j] = make_float4(val.x, val.y, nxt.x, nxt.y);
}

// ---------------------------------------------------------------------------
// backprojection + update with BOTH symmetries:
//  - 90-degree pairing: one geometry eval serves angles v and v+96
//  - 180-degree point-mirror: the SAME eval also serves pixel pm = 65535-p
//    with weights P^m_ab = P_{(1-a)(1-b)}:
//      (v,   pm): q1 @ det 254-j0,  q0 @ det 255-j0
//      (v+96,pm): r1 @ det k0,      r0 @ det k0+1
// Layout: 512 threads = 8 angle-slices x 64 top-half pixels (grid 512 ->
// 8192 warps, occupancy preserved). Fixed-order smem combine (deterministic).
// ---------------------------------------------------------------------------
__global__ void __launch_bounds__(512, 3) bwd_kernel(const float* __restrict__ wptr,
                                                     float* __restrict__ out) {
    __shared__ float4 sg[96];
    __shared__ float2 sOwn[8][64];
    __shared__ float2 sMir[8][64];
    const int tid = threadIdx.x;
    if (tid < 96) sg[tid] = g_trig4[tid];
    __syncthreads();

    const int pxi   = tid & 63;
    const int slice = tid >> 6;              // 0..7
    const int p  = blockIdx.x * 64 + pxi;    // top-half pixel (iy in [0,128))
    const int ix = p & (W - 1);
    const int iy = p >> 8;
    const float px = (float)ix - 127.5f;
    const float py = (float)iy - 127.5f;
    const float npx = -px;

    float accA0 = 0.f, accB0 = 0.f, accA1 = 0.f, accB1 = 0.f;  // own pixel
    float accAm = 0.f, accBm = 0.f;                            // mirror pixel
    const int v0 = slice * 12;
    const float4* __restrict__ row  = g_pair + v0 * D;          // angle v
    const float4* __restrict__ rowm = g_pair + (96 + v0) * D;   // angle v+96

    #pragma unroll 2
    for (int v = v0; v < v0 + 12; ++v, row += D, rowm += D) {
        const float4 q = sg[v];
        const float svDP = q.x, cvDP = q.y, svI = q.z, cvI = q.w;

        const float jc = fmaf(py, cvI, fmaf(npx, svI, 127.5f));
        const float kc = fmaf(px, cvI, fmaf(py,  svI, 127.5f));
        const float jf = floorf(jc), kf = floorf(kc);
        const float fj = jc - jf,    fk = kc - kf;
        const int   j0 = (int)jf;
        const int   k0 = (int)kf;

        const float dx00 = fmaf(fj, svDP, -(fk * cvDP));
        const float u    = fmaf(fj, cvDP,  (fk * svDP));
        const float dx10 = dx00 - svDP;
        const float dx01 = dx00 + cvDP;
        const float dx11 = dx10 + cvDP;
        const float e10  = u - cvDP;
        const float e01  = u - svDP;
        const float e11  = e10 - svDP;

        const float hx00 = __saturatef(1.f - fabsf(dx00));
        const float hx10 = __saturatef(1.f - fabsf(dx10));
        const float hx01 = __saturatef(1.f - fabsf(dx01));
        const float hx11 = __saturatef(1.f - fabsf(dx11));
        const float hy00 = __saturatef(1.f - fabsf(u));
        const float hy10 = __saturatef(1.f - fabsf(e10));
        const float hy01 = __saturatef(1.f - fabsf(e01));
        const float hy11 = __saturatef(1.f - fabsf(e11));

        const float P00 = hx00 * hy00;
        const float P10 = hx10 * hy10;
        const float P01 = hx01 * hy01;
        const float P11 = hx11 * hy11;

        const float q0 = P00 + P01, q1 = P10 + P11;   // angle v
        const float r0 = P01 + P11, r1 = P00 + P10;   // angle v+96

        const float4 t01 = __ldg(row  + j0);          // (v, p)
        const float4 m01 = __ldg(rowm + (254 - k0));  // (v+96, p)
        const float4 tm  = __ldg(row  + (254 - j0));  // (v, pm)
        const float4 mm  = __ldg(rowm + k0);          // (v+96, pm)
        accA0 = fmaf(t01.x, q0, fmaf(t01.z, q1, accA0));
        accB0 = fmaf(t01.y, q0, fmaf(t01.w, q1, accB0));
        accA1 = fmaf(m01.x, r0, fmaf(m01.z, r1, accA1));
        accB1 = fmaf(m01.y, r0, fmaf(m01.w, r1, accB1));
        accAm = fmaf(tm.x, q1, fmaf(tm.z, q0, fmaf(mm.x, r1, fmaf(mm.z, r0, accAm))));
        accBm = fmaf(tm.y, q1, fmaf(tm.w, q0, fmaf(mm.y, r1, fmaf(mm.w, r0, accBm))));
    }

    sOwn[slice][pxi] = make_float2(accA0 + accA1, accB0 + accB1);
    sMir[slice][pxi] = make_float2(accAm, accBm);
    __syncthreads();

    if (tid < 64) {                 // own pixels, fixed-order combine
        float a = 0.f, b = 0.f;
        #pragma unroll
        for (int s = 0; s < 8; ++s) { float2 t = sOwn[s][tid]; a += t.x; b += t.y; }
        const float wdt = __ldg(wptr) * DTf;
        const int pp = blockIdx.x * 64 + tid;
        const float2 ia = g_img2[pp];
        out[pp]      = fmaf(-wdt, a, ia.x);
        out[pp + HW] = fmaf(-wdt, b, ia.y);
    } else if (tid < 128) {         // mirror pixels
        const int i = tid - 64;
        float a = 0.f, b = 0.f;
        #pragma unroll
        for (int s = 0; s < 8; ++s) { float2 t = sMir[s][i]; a += t.x; b += t.y; }
        const float wdt = __ldg(wptr) * DTf;
        const int pm = (HW - 1) - (blockIdx.x * 64 + i);
        const float2 ia = g_img2[pm];
        out[pm]      = fmaf(-wdt, a, ia.x);
        out[pm + HW] = fmaf(-wdt, b, ia.y);
    }
}

// ---------------------------------------------------------------------------
extern "C" void kernel_launch(void* const* d_in, const int* in_sizes, int n_in,
                              void* d_out, int out_size) {
    const float* img  = (const float*)d_in[0];   // [2,1,256,256]
    const float* proj = (const float*)d_in[1];   // [2,1,192,256]
    const float* wptr = (const float*)d_in[2];   // [1]
    float* out = (float*)d_out;                  // [2,1,256,256]

    prep_kernel<<<256, 256>>>(img);
    fwd2_kernel<<<768, 256>>>(proj);
    combine_kernel<<<192, 256>>>(proj);
    bwd_kernel<<<HW / 128, 512>>>(wptr, out);    // 512 blocks x (8 slices x 64 px)
}

// round 17
// speedup vs baseline: 1.2589x; 1.1445x over previous
#include <cuda_runtime.h>
#include <cuda_fp16.h>
#include <math.h>

#define H 256
#define W 256
#define V 192
#define D 256
#define S 256
#define HW (H*W)
#define PW 264              /* padded stride: data at [2,257], frame [0,259] */

#define SQRT2_D 1.4142135623730951
#define DPf     ((float)(2.0 * SQRT2_D * 128.0 / 255.0))   /* sample spacing, px */
#define OFFf    ((float)(-SQRT2_D * 128.0))
#define INV_DPf ((float)(255.0 / (256.0 * SQRT2_D)))
#define DTf     ((float)(2.0 * SQRT2_D / 256.0))
#define PI_D    3.141592653589793

// quad cell: 8 x fp16 = (A,B) at slots {(0,0),(fast+1),(slow+1),(both+1)}
__device__ uint4  g_quadN[PW * PW]; // normal: fast=x, slow=y
__device__ uint4  g_quadT[PW * PW]; // transposed: fast=y, slow=x
__device__ float2 g_img2 [HW];      // fp32 interleave (bwd final update)
__device__ float2 g_temp [V * D];   // residual sinogram rows v<96 (A,B)
__device__ float4 g_pair [V * D];   // (temp[j], temp[j+1]) x both images
__device__ float  g_colA [8 * 96 * 256];  // column partial sums, 8 row-groups
__device__ float  g_colB [8 * 96 * 256];
__device__ float4 g_trig4[96];      // {svDP, cvDP, svI, cvI} for bwd
__device__ float2 g_trigB[96];      // raw {cv, sv} for fwd2

__device__ __forceinline__ unsigned packh2(float a, float b) {
    __half2 h = __floats2half2_rn(a, b);
    return *reinterpret_cast<unsigned*>(&h);
}

// ---------------------------------------------------------------------------
// prep: build fp16 quad images (normal + transposed) from a 17x17-halo smem
// tile (coalesced), exact border-frame slot fixups, fp32 interleave, trig.
// ---------------------------------------------------------------------------
__global__ void __launch_bounds__(256) prep_kernel(const float* __restrict__ img) {
    __shared__ float2 s[17][17];
    const int tid = threadIdx.x;
    const int tx = tid & 15, ty = tid >> 4;
    const int bx = (blockIdx.x & 15) << 4;
    const int by = (blockIdx.x >> 4) << 4;

    for (int i = tid; i < 289; i += 256) {
        int r = i / 17, c = i - r * 17;
        int y = by + r, x = bx + c;
        float2 val = make_float2(0.f, 0.f);
        if (x < W && y < H) val = make_float2(img[y * W + x], img[y * W + x + HW]);
        s[r][c] = val;
    }
    __syncthreads();

    {   // normal quad + fp32 interleave
        int x = bx + tx, y = by + ty;
        float2 v0 = s[ty][tx],     v1 = s[ty][tx + 1];
        float2 v2 = s[ty + 1][tx], v3 = s[ty + 1][tx + 1];
        g_img2[y * W + x] = v0;
        g_quadN[(y + 2) * PW + (x + 2)] =
            make_uint4(packh2(v0.x, v0.y), packh2(v1.x, v1.y),
                       packh2(v2.x, v2.y), packh2(v3.x, v3.y));
    }
    {   // transposed quad: cell(row=X+2, col=Y+2), X=bx+ty, Y=by+tx
        float2 u0 = s[tx][ty],     u1 = s[tx + 1][ty];     // (Y,X), (Y+1,X)
        float2 u2 = s[tx][ty + 1], u3 = s[tx + 1][ty + 1]; // (Y,X+1),(Y+1,X+1)
        g_quadT[(bx + ty + 2) * PW + (by + tx + 2)] =
            make_uint4(packh2(u0.x, u0.y), packh2(u1.x, u1.y),
                       packh2(u2.x, u2.y), packh2(u3.x, u3.y));
    }

    // border frame: [0,259]^2 minus [2,257]^2 = 2064 cells per array.
    // Each slot filled exactly: slot(ds,df) -> img[slow0+ds / fast0+df] if in range.
    if (blockIdx.x < 2) {
        const bool isN = (blockIdx.x == 0);
        uint4* dst = isN ? g_quadN : g_quadT;
        for (int i = tid; i < 2064; i += 256) {
            int r, c;
            if (i < 1040) {                    // rows {0,1,258,259} x cols [0,259]
                int rr = i / 260;  c = i - rr * 260;
                r = (rr < 2) ? rr : (256 + rr);
            } else {                           // cols {0,1,258,259} x rows [2,257]
                int j = i - 1040;
                int cc = j / 256;  r = 2 + (j - cc * 256);
                c = (cc < 2) ? cc : (256 + cc);
            }
            const int slow0 = r - 2, fast0 = c - 2;
            unsigned w4[4];
            #pragma unroll
            for (int sl = 0; sl < 4; ++sl) {
                int df = sl & 1, ds = sl >> 1;
                int yy = isN ? (slow0 + ds) : (fast0 + df);
                int xx = isN ? (fast0 + df) : (slow0 + ds);
                float a = 0.f, b = 0.f;
                if ((unsigned)yy < (unsigned)H && (unsigned)xx < (unsigned)W) {
                    a = img[yy * W + xx];
                    b = img[yy * W + xx + HW];
                }
                w4[sl] = packh2(a, b);
            }
            dst[r * PW + c] = make_uint4(w4[0], w4[1], w4[2], w4[3]);
        }
    }

    if (blockIdx.x < 96 && tid == 0) {
        const int v = blockIdx.x;
        float cv, sv;
        float af = (float)((double)v * (PI_D / 192.0));
        sincosf(af, &sv, &cv);
        g_trigB[v] = make_float2(cv, sv);
        g_trig4[v] = make_float4(sv * DPf, cv * DPf, sv * INV_DPf, cv * INV_DPf);
    }
}

// ---------------------------------------------------------------------------
// fwd2: sample field F_v[j][k] for base angles v<96 serves BOTH sinogram
// halves (90-degree identity). Warp-per-row (lanes along k). fp16 quad image:
// ONE LDG.128 per bilinear sample (both images, all 4 corners).
// ---------------------------------------------------------------------------
__global__ void __launch_bounds__(256) fwd2_kernel(const float* __restrict__ proj) {
    __shared__ float2 shW[8][256];               // per-warp column partials
    const int bid = blockIdx.x;
    const int v   = bid >> 3;
    const int grp = bid & 7;
    const int tid = threadIdx.x;
    const int warp = tid >> 5, lane = tid & 31;

    const float2 tv = g_trigB[v];
    const float cv = tv.x, sv = tv.y;
    const bool steep = fabsf(sv) > fabsf(cv);
    const uint4* __restrict__ im4 = steep ? g_quadT : g_quadN;
    const float c2 = steep ? sv : cv;
    const float s2 = steep ? cv : sv;

    float cA[8], cB[8];
    #pragma unroll
    for (int c = 0; c < 8; ++c) { cA[c] = 0.f; cB[c] = 0.f; }

    #pragma unroll 1
    for (int r = 0; r < 4; ++r) {
        const int j = (grp << 5) + (r << 3) + warp;
        const float s128 = fmaf((float)j, DPf, OFFf);
        const float ax0 = fmaf(-s128, sv, 129.5f);   // padded (+2)
        const float ay0 = fmaf( s128, cv, 129.5f);
        const float aX = steep ? ay0 : ax0;
        const float aY = steep ? ax0 : ay0;
        const float bX = fmaf(OFFf, c2, aX), sX = DPf * c2;   // X(k) = bX + k*sX
        const float bY = fmaf(OFFf, s2, aY), sY = DPf * s2;

        float lo = 0.f, hi = 255.f;
        bool empty = false;
        {
            float rr = 1.0f / sX;
            float t1 = (0.999f - bX) * rr, t2 = (258.001f - bX) * rr;
            lo = fmaxf(lo, fminf(t1, t2)); hi = fminf(hi, fmaxf(t1, t2));
        }
        if (fabsf(sY) > 1e-6f) {
            float rr = 1.0f / sY;
            float t1 = (0.999f - bY) * rr, t2 = (258.001f - bY) * rr;
            lo = fmaxf(lo, fminf(t1, t2)); hi = fminf(hi, fmaxf(t1, t2));
        } else if (bY < 0.999f || bY > 258.001f) empty = true;

        int klo = (int)ceilf(lo), khi = (int)floorf(hi);
        float rowA = 0.f, rowB = 0.f;
        if (!empty && klo <= khi) {
            const int c0 = klo >> 5, c1 = khi >> 5;
            #pragma unroll
            for (int c = 0; c < 8; ++c) {
                if (c >= c0 && c <= c1) {           // warp-uniform branch
                    const int k = (c << 5) + lane;
                    const float pred = (k >= klo && k <= khi) ? 1.f : 0.f;
                    float X = fmaf((float)k, sX, bX);
                    float Y = fmaf((float)k, sY, bY);
                    X = fminf(fmaxf(X, 0.f), 258.f);   // safe for pred=0 lanes
                    Y = fminf(fmaxf(Y, 0.f), 258.f);
                    float Xf = floorf(X), Yf = floorf(Y);
                    float fx = X - Xf, fy = Y - Yf;
                    int base = (int)Yf * PW + (int)Xf;
                    uint4 qv = __ldg(im4 + base);      // all 4 corners x 2 imgs
                    float2 s0 = __half22float2(*reinterpret_cast<const __half2*>(&qv.x));
                    float2 s1 = __half22float2(*reinterpret_cast<const __half2*>(&qv.y));
                    float2 s2v = __half22float2(*reinterpret_cast<const __half2*>(&qv.z));
                    float2 s3 = __half22float2(*reinterpret_cast<const __half2*>(&qv.w));
                    float gx = 1.f - fx, gy = 1.f - fy;
                    float w00 = gx * gy, w10 = fx * gy, w01 = gx * fy, w11 = fx * fy;
                    float fa = fmaf(s0.x, w00, fmaf(s1.x, w10, fmaf(s2v.x, w01, s3.x * w11)));
                    float fb = fmaf(s0.y, w00, fmaf(s1.y, w10, fmaf(s2v.y, w01, s3.y * w11)));
                    fa *= pred; fb *= pred;
                    rowA += fa;  rowB += fb;
                    cA[c] += fa; cB[c] += fb;
                }
            }
        }
        #pragma unroll
        for (int o = 16; o; o >>= 1) {
            rowA += __shfl_xor_sync(0xffffffffu, rowA, o);
            rowB += __shfl_xor_sync(0xffffffffu, rowB, o);
        }
        if (lane == 0) {
            int idx = v * D + j;
            g_temp[idx] = make_float2(fmaf(DTf, rowA, -__ldg(proj + idx)),
                                      fmaf(DTf, rowB, -__ldg(proj + idx + V * D)));
        }
    }

    // deterministic column reduction: warp slices -> smem -> fixed-order sum
    #pragma unroll
    for (int c = 0; c < 8; ++c)
        shW[warp][(c << 5) + lane] = make_float2(cA[c], cB[c]);
    __syncthreads();
    float a = 0.f, b = 0.f;
    #pragma unroll
    for (int w = 0; w < 8; ++w) {
        float2 t = shW[w][tid];
        a += t.x; b += t.y;
    }
    g_colA[((grp * 96 + v) << 8) + tid] = a;
    g_colB[((grp * 96 + v) << 8) + tid] = b;
}

// ---------------------------------------------------------------------------
// combine: finalize sinogram rows v>=96 (fixed-order, deterministic) and
// build the float4 pair array (t[j], t[j+1]) for bwd.
// ---------------------------------------------------------------------------
__global__ void __launch_bounds__(256) combine_kernel(const float* __restrict__ proj) {
    __shared__ float2 sval[256];
    const int v = blockIdx.x;          // 0..191
    const int j = threadIdx.x;
    float2 val;
    if (v < 96) {
        val = g_temp[v * D + j];
    } else {
        const int vb = v - 96;
        const int kk = 255 - j;
        float a = 0.f, b = 0.f;
        #pragma unroll
        for (int g = 0; g < 8; ++g) {
            a += g_colA[((g * 96 + vb) << 8) + kk];
            b += g_colB[((g * 96 + vb) << 8) + kk];
        }
        int idx = v * D + j;
        val = make_float2(fmaf(DTf, a, -__ldg(proj + idx)),
                          fmaf(DTf, b, -__ldg(proj + idx + V * D)));
    }
    sval[j] = val;
    __syncthreads();
    float2 nxt = sval[min(j + 1, 255)];
    g_pair[(v << 8) + j] = make_float4(val.x, val.y, nxt.x, nxt.y);
}

// ---------------------------------------------------------------------------
// backprojection + update with 90-deg + 180-deg symmetries (4-way reuse).
// 8 angle-slices x 64 top-half pixels; fixed-order smem combine.
// unroll 1 to shed registers and recover occupancy (R12/R15 lesson).
// ---------------------------------------------------------------------------
__global__ void __launch_bounds__(512, 3) bwd_kernel(const float* __restrict__ wptr,
                                                     float* __restrict__ out) {
    __shared__ float4 sg[96];
    __shared__ float2 sOwn[8][64];
    __shared__ float2 sMir[8][64];
    const int tid = threadIdx.x;
    if (tid < 96) sg[tid] = g_trig4[tid];
    __syncthreads();

    const int pxi   = tid & 63;
    const int slice = tid >> 6;              // 0..7
    const int p  = blockIdx.x * 64 + pxi;    // top-half pixel
    const int ix = p & (W - 1);
    const int iy = p >> 8;
    const float px = (float)ix - 127.5f;
    const float py = (float)iy - 127.5f;
    const float npx = -px;

    float accA0 = 0.f, accB0 = 0.f, accA1 = 0.f, accB1 = 0.f;  // own pixel
    float accAm = 0.f, accBm = 0.f;                            // mirror pixel
    const int v0 = slice * 12;
    const float4* __restrict__ row  = g_pair + v0 * D;          // angle v
    const float4* __restrict__ rowm = g_pair + (96 + v0) * D;   // angle v+96

    #pragma unroll 1
    for (int v = v0; v < v0 + 12; ++v, row += D, rowm += D) {
        const float4 q = sg[v];
        const float svDP = q.x, cvDP = q.y, svI = q.z, cvI = q.w;

        const float jc = fmaf(py, cvI, fmaf(npx, svI, 127.5f));
        const float kc = fmaf(px, cvI, fmaf(py,  svI, 127.5f));
        const float jf = floorf(jc), kf = floorf(kc);
        const float fj = jc - jf,    fk = kc - kf;
        const int   j0 = (int)jf;
        const int   k0 = (int)kf;

        const float dx00 = fmaf(fj, svDP, -(fk * cvDP));
        const float u    = fmaf(fj, cvDP,  (fk * svDP));
        const float dx10 = dx00 - svDP;
        const float dx01 = dx00 + cvDP;
        const float dx11 = dx10 + cvDP;
        const float e10  = u - cvDP;
        const float e01  = u - svDP;
        const float e11  = e10 - svDP;

        const float hx00 = __saturatef(1.f - fabsf(dx00));
        const float hx10 = __saturatef(1.f - fabsf(dx10));
        const float hx01 = __saturatef(1.f - fabsf(dx01));
        const float hx11 = __saturatef(1.f - fabsf(dx11));
        const float hy00 = __saturatef(1.f - fabsf(u));
        const float hy10 = __saturatef(1.f - fabsf(e10));
        const float hy01 = __saturatef(1.f - fabsf(e01));
        const float hy11 = __saturatef(1.f - fabsf(e11));

        const float P00 = hx00 * hy00;
        const float P10 = hx10 * hy10;
        const float P01 = hx01 * hy01;
        const float P11 = hx11 * hy11;

        const float q0 = P00 + P01, q1 = P10 + P11;   // angle v
        const float r0 = P01 + P11, r1 = P00 + P10;   // angle v+96

        const float4 t01 = __ldg(row  + j0);          // (v, p)
        const float4 m01 = __ldg(rowm + (254 - k0));  // (v+96, p)
        const float4 tm  = __ldg(row  + (254 - j0));  // (v, pm)
        const float4 mm  = __ldg(rowm + k0);          // (v+96, pm)
        accA0 = fmaf(t01.x, q0, fmaf(t01.z, q1, accA0));
        accB0 = fmaf(t01.y, q0, fmaf(t01.w, q1, accB0));
        accA1 = fmaf(m01.x, r0, fmaf(m01.z, r1, accA1));
        accB1 = fmaf(m01.y, r0, fmaf(m01.w, r1, accB1));
        accAm = fmaf(tm.x, q1, fmaf(tm.z, q0, fmaf(mm.x, r1, fmaf(mm.z, r0, accAm))));
        accBm = fmaf(tm.y, q1, fmaf(tm.w, q0, fmaf(mm.y, r1, fmaf(mm.w, r0, accBm))));
    }

    sOwn[slice][pxi] = make_float2(accA0 + accA1, accB0 + accB1);
    sMir[slice][pxi] = make_float2(accAm, accBm);
    __syncthreads();

    if (tid < 64) {                 // own pixels, fixed-order combine
        float a = 0.f, b = 0.f;
        #pragma unroll
        for (int s = 0; s < 8; ++s) { float2 t = sOwn[s][tid]; a += t.x; b += t.y; }
        const float wdt = __ldg(wptr) * DTf;
        const int pp = blockIdx.x * 64 + tid;
        const float2 ia = g_img2[pp];
        out[pp]      = fmaf(-wdt, a, ia.x);
        out[pp + HW] = fmaf(-wdt, b, ia.y);
    } else if (tid < 128) {         // mirror pixels
        const int i = tid - 64;
        float a = 0.f, b = 0.f;
        #pragma unroll
        for (int s = 0; s < 8; ++s) { float2 t = sMir[s][i]; a += t.x; b += t.y; }
        const float wdt = __ldg(wptr) * DTf;
        const int pm = (HW - 1) - (blockIdx.x * 64 + i);
        const float2 ia = g_img2[pm];
        out[pm]      = fmaf(-wdt, a, ia.x);
        out[pm + HW] = fmaf(-wdt, b, ia.y);
    }
}

// ---------------------------------------------------------------------------
extern "C" void kernel_launch(void* const* d_in, const int* in_sizes, int n_in,
                              void* d_out, int out_size) {
    const float* img  = (const float*)d_in[0];   // [2,1,256,256]
    const float* proj = (const float*)d_in[1];   // [2,1,192,256]
    const float* wptr = (const float*)d_in[2];   // [1]
    float* out = (float*)d_out;                  // [2,1,256,256]

    prep_kernel<<<256, 256>>>(img);
    fwd2_kernel<<<768, 256>>>(proj);
    combine_kernel<<<192, 256>>>(proj);
    bwd_kernel<<<HW / 128, 512>>>(wptr, out);
}